// round 16
// baseline (speedup 1.0000x reference)
#include <cuda_runtime.h>

// Problem constants (fixed by the reference): B=4, S=2048, E=16, H=4, D_K=4
#define BB 4
#define SS 2048
#define EE 16
#define HH 4
#define DK 4
#define NBH (BB*HH)

#define KSPLIT 16
#define KT (SS/KSPLIT)       // 128 keys per split tile
#define THREADS 128
#define QPT 4                // 4 queries/thread = 2 packed query-pairs
#define QBLK (THREADS*QPT)   // 512 queries per CTA

typedef unsigned long long u64;

// Scratch (allocation-free rule: __device__ globals)
// Layout: parta[ks][h][b][sq] as float4 rows; partl[ks][h][b][sq] scalar.
__device__ float g_parta[KSPLIT * BB * SS * EE];
__device__ float g_partl[KSPLIT * BB * SS * HH];

__device__ __forceinline__ float ex2f(float x) {
    float y; asm("ex2.approx.ftz.f32 %0, %1;" : "=f"(y) : "f"(x)); return y;
}
__device__ __forceinline__ u64 pk2(float lo, float hi) {
    u64 r; asm("mov.b64 %0, {%1, %2};" : "=l"(r) : "f"(lo), "f"(hi)); return r;
}
__device__ __forceinline__ void upk2(u64 v, float& lo, float& hi) {
    asm("mov.b64 {%0, %1}, %2;" : "=f"(lo), "=f"(hi) : "l"(v));
}
__device__ __forceinline__ u64 fma2(u64 a, u64 b, u64 c) {
    u64 d; asm("fma.rn.f32x2 %0, %1, %2, %3;" : "=l"(d) : "l"(a), "l"(b), "l"(c)); return d;
}
__device__ __forceinline__ u64 mul2(u64 a, u64 b) {
    u64 d; asm("mul.rn.f32x2 %0, %1, %2;" : "=l"(d) : "l"(a), "l"(b)); return d;
}
__device__ __forceinline__ u64 add2(u64 a, u64 b) {
    u64 d; asm("add.rn.f32x2 %0, %1, %2;" : "=l"(d) : "l"(a), "l"(b)); return d;
}

// ---------------------------------------------------------------------------
// Fused kernel: per-CTA K/V projection + attention partials.
// QUERY-PAIR packing: qp[d] = (qA_d, qB_d); K/V stored dim-duplicated
// ((k_d,k_d)) so one fma2 advances two queries against one key.
// Accumulators (A_qA[d], A_qB[d]) -> persistent regs ~36; __launch_bounds__
// (128,7) targets 7 CTAs/SM = single wave for the 1024-CTA grid.
// Bounded scores -> no max subtraction. Scale folded into Wk.
// ---------------------------------------------------------------------------
__global__ void __launch_bounds__(THREADS, 7)
attn_kernel(const float* __restrict__ x,
            const float* __restrict__ theta,
            const float* __restrict__ Wk,
            const float* __restrict__ Wv) {
    __shared__ ulonglong2 K01[KT];       // ((k0,k0),(k1,k1)) per key
    __shared__ ulonglong2 K23[KT];       // ((k2,k2),(k3,k3))
    __shared__ ulonglong2 V01[KT];
    __shared__ ulonglong2 V23[KT];
    __shared__ float wk[DK * EE];
    __shared__ float wv[DK * EE];

    int tid = threadIdx.x;               // 0..127
    int qb  = blockIdx.x;                // 0..3
    int bh  = blockIdx.y;                // 0..15
    int ks  = blockIdx.z;                // 0..15
    int b = bh >> 2, h = bh & 3;

    const float SCL = 0.72134752044448170368f;   // 0.5 * log2(e)
    if (tid < DK * EE) {
        wk[tid] = Wk[h * DK * EE + tid] * SCL;   // fold score scale into K
        wv[tid] = Wv[h * DK * EE + tid];
    }

    // ---- queries: 2 packed pairs (qA,qB) = (sq0+qp*256, sq0+qp*256+128) ----
    const float4 thv = *reinterpret_cast<const float4*>(theta + h * DK);
    u64 qp0[2], qp1[2], qp2[2], qp3[2];
    int sq0 = qb * QBLK + tid;
    #pragma unroll
    for (int qp = 0; qp < 2; qp++) {
        int sqA = sq0 + qp * 2 * THREADS;
        int sqB = sqA + THREADS;
        const float4 xa = *reinterpret_cast<const float4*>(
            x + (b * SS + sqA) * EE + h * DK);
        const float4 xb = *reinterpret_cast<const float4*>(
            x + (b * SS + sqB) * EE + h * DK);
        qp0[qp] = pk2(__cosf(xa.x + thv.x), __cosf(xb.x + thv.x));
        qp1[qp] = pk2(__cosf(xa.y + thv.y), __cosf(xb.y + thv.y));
        qp2[qp] = pk2(__cosf(xa.z + thv.z), __cosf(xb.z + thv.z));
        qp3[qp] = pk2(__cosf(xa.w + thv.w), __cosf(xb.w + thv.w));
    }
    __syncthreads();

    // ---- K/V tile build: one token per thread (KT == THREADS) ----
    {
        int tok = tid;
        const float4* x4 = reinterpret_cast<const float4*>(
            x + ((b * SS + ks * KT) + tok) * EE);
        float xr[EE];
        #pragma unroll
        for (int r = 0; r < 4; r++) {
            float4 q = x4[r];
            xr[4*r+0] = q.x; xr[4*r+1] = q.y; xr[4*r+2] = q.z; xr[4*r+3] = q.w;
        }
        float kk[DK], vv[DK];
        #pragma unroll
        for (int d = 0; d < DK; d++) {
            float a = 0.f, c = 0.f;
            #pragma unroll
            for (int e = 0; e < EE; e++) {
                a = fmaf(xr[e], wk[d * EE + e], a);
                c = fmaf(xr[e], wv[d * EE + e], c);
            }
            kk[d] = a; vv[d] = c;
        }
        ulonglong2 t0, t1;
        t0.x = pk2(kk[0], kk[0]); t0.y = pk2(kk[1], kk[1]);
        t1.x = pk2(kk[2], kk[2]); t1.y = pk2(kk[3], kk[3]);
        K01[tok] = t0; K23[tok] = t1;
        t0.x = pk2(vv[0], vv[0]); t0.y = pk2(vv[1], vv[1]);
        t1.x = pk2(vv[2], vv[2]); t1.y = pk2(vv[3], vv[3]);
        V01[tok] = t0; V23[tok] = t1;
    }
    __syncthreads();

    // accumulators: (A_qA[d], A_qB[d]) per query-pair, plus (lA,lB)
    u64 A0[2], A1[2], A2[2], A3[2], L[2];
    #pragma unroll
    for (int qp = 0; qp < 2; qp++) {
        A0[qp] = 0ULL; A1[qp] = 0ULL; A2[qp] = 0ULL; A3[qp] = 0ULL; L[qp] = 0ULL;
    }

    #pragma unroll 4
    for (int j = 0; j < KT; j++) {
        ulonglong2 k01 = K01[j];             // broadcast LDS.128
        ulonglong2 k23 = K23[j];
        ulonglong2 v01 = V01[j];
        ulonglong2 v23 = V23[j];
        #pragma unroll
        for (int qp = 0; qp < 2; qp++) {
            u64 s = mul2(qp0[qp], k01.x);
            s = fma2(qp1[qp], k01.y, s);
            s = fma2(qp2[qp], k23.x, s);
            s = fma2(qp3[qp], k23.y, s);      // (score_qA, score_qB)
            float sa, sb; upk2(s, sa, sb);
            u64 pp = pk2(ex2f(sa), ex2f(sb));
            L[qp]  = add2(L[qp], pp);
            A0[qp] = fma2(pp, v01.x, A0[qp]);
            A1[qp] = fma2(pp, v01.y, A1[qp]);
            A2[qp] = fma2(pp, v23.x, A2[qp]);
            A3[qp] = fma2(pp, v23.y, A3[qp]);
        }
    }

    // coalesced partial stores: [ks][h][b][sq] (lane-consecutive sq)
    int rowbase = ((ks * HH + h) * BB + b) * SS;
    #pragma unroll
    for (int qp = 0; qp < 2; qp++) {
        int sqA = sq0 + qp * 2 * THREADS;
        int sqB = sqA + THREADS;
        float a0A, a0B, a1A, a1B, a2A, a2B, a3A, a3B, lA, lB;
        upk2(A0[qp], a0A, a0B); upk2(A1[qp], a1A, a1B);
        upk2(A2[qp], a2A, a2B); upk2(A3[qp], a3A, a3B);
        upk2(L[qp], lA, lB);
        reinterpret_cast<float4*>(g_parta)[rowbase + sqA] =
            make_float4(a0A, a1A, a2A, a3A);
        g_partl[rowbase + sqA] = lA;
        reinterpret_cast<float4*>(g_parta)[rowbase + sqB] =
            make_float4(a0B, a1B, a2B, a3B);
        g_partl[rowbase + sqB] = lB;
    }
}

// ---------------------------------------------------------------------------
// Epilogue (FROZEN, round-13 best): CTA = 16 tokens, 256 threads.
// Thread = (sg = tid>>6, token-head = tid&63); 4 ks-planes per thread,
// 4-lines/LDG; smem combine (stride-5); 64 threads do out = att @ Wc^T.
// ---------------------------------------------------------------------------
#define EPI_TOK 16
#define EPI_THREADS 256
#define SPLANE (BB * SS)     // float4-row stride between h groups

__global__ void __launch_bounds__(EPI_THREADS)
epi_kernel(const float* __restrict__ Wc, float* __restrict__ out) {
    __shared__ float wct[EE * EE];            // wct[e*16+o] = Wc[o*16+e]
    __shared__ float ps[4 * 64 * 5];          // [sg][token-head][5], stride-5
    __shared__ float att[EPI_TOK][EE + 1];

    int tid = threadIdx.x;                    // 0..255
    wct[(tid & 15) * EE + (tid >> 4)] = Wc[tid];

    int sg    = tid >> 6;                     // split-group 0..3 (4 ks each)
    int local = tid & 63;                     // token-head
    int tl = local >> 2;                      // local token 0..15
    int h  = local & 3;
    int tok = blockIdx.x * EPI_TOK + tl;
    int b  = tok >> 11;
    int sq = tok & (SS - 1);

    const float4* pa = reinterpret_cast<const float4*>(g_parta);
    const float*  pl = g_partl;
    int base = (h * BB + b) * SS + sq;        // ks=0 row
    int i0 = base + (sg * 4 + 0) * (HH * SPLANE);
    int i1 = base + (sg * 4 + 1) * (HH * SPLANE);
    int i2 = base + (sg * 4 + 2) * (HH * SPLANE);
    int i3 = base + (sg * 4 + 3) * (HH * SPLANE);

    float4 t0 = pa[i0], t1 = pa[i1], t2 = pa[i2], t3 = pa[i3];
    float  u0 = pl[i0], u1 = pl[i1], u2 = pl[i2], u3 = pl[i3];

    float ax = (t0.x + t1.x) + (t2.x + t3.x);
    float ay = (t0.y + t1.y) + (t2.y + t3.y);
    float az = (t0.z + t1.z) + (t2.z + t3.z);
    float aw = (t0.w + t1.w) + (t2.w + t3.w);
    float l  = (u0 + u1) + (u2 + u3);

    float* row = ps + tid * 5;                // stride 5: conflict-free
    row[0] = ax; row[1] = ay; row[2] = az; row[3] = aw; row[4] = l;
    __syncthreads();

    if (tid < 64) {
        const float* p0 = ps + tid * 5;
        const float* p1 = p0 + 64 * 5;
        const float* p2 = p1 + 64 * 5;
        const float* p3 = p2 + 64 * 5;
        float a0 = (p0[0] + p1[0]) + (p2[0] + p3[0]);
        float a1 = (p0[1] + p1[1]) + (p2[1] + p3[1]);
        float a2 = (p0[2] + p1[2]) + (p2[2] + p3[2]);
        float a3 = (p0[3] + p1[3]) + (p2[3] + p3[3]);
        float ll = (p0[4] + p1[4]) + (p2[4] + p3[4]);
        float inv = 1.0f / ll;
        float* arow = att[tl] + h * DK;
        arow[0] = a0 * inv; arow[1] = a1 * inv;
        arow[2] = a2 * inv; arow[3] = a3 * inv;
    }
    __syncthreads();

    if (tid < 64) {
        const float* ar = att[tl];
        float r[4] = {0.f, 0.f, 0.f, 0.f};
        #pragma unroll
        for (int e = 0; e < EE; e++) {
            float av = ar[e];
            #pragma unroll
            for (int d = 0; d < 4; d++)
                r[d] = fmaf(av, wct[e * EE + h * 4 + d], r[d]);
        }
        reinterpret_cast<float4*>(out + tok * EE)[h] =
            make_float4(r[0], r[1], r[2], r[3]);
    }
}

// ---------------------------------------------------------------------------
extern "C" void kernel_launch(void* const* d_in, const int* in_sizes, int n_in,
                              void* d_out, int out_size) {
    const float* x     = (const float*)d_in[0];
    const float* theta = (const float*)d_in[1];
    const float* Wk    = (const float*)d_in[2];
    const float* Wv    = (const float*)d_in[3];
    const float* Wc    = (const float*)d_in[4];
    float* out = (float*)d_out;

    attn_kernel<<<dim3(SS / QBLK, NBH, KSPLIT), THREADS>>>(x, theta, Wk, Wv);
    epi_kernel<<<(BB * SS) / EPI_TOK, EPI_THREADS>>>(Wc, out);
}

// round 17
// speedup vs baseline: 1.1115x; 1.1115x over previous
#include <cuda_runtime.h>

// Problem constants (fixed by the reference): B=4, S=2048, E=16, H=4, D_K=4
#define BB 4
#define SS 2048
#define EE 16
#define HH 4
#define DK 4
#define NBH (BB*HH)

#define KSPLIT 16
#define KT (SS/KSPLIT)       // 128 keys per split tile
#define THREADS 128
#define QPT 4
#define QBLK (THREADS*QPT)   // 512 queries per CTA

typedef unsigned long long u64;

// Scratch (allocation-free rule: __device__ globals)
// Layout: parta[ks][h][b][sq] as float4 rows; partl[ks][h][b][sq] scalar.
__device__ float g_parta[KSPLIT * BB * SS * EE];
__device__ float g_partl[KSPLIT * BB * SS * HH];

__device__ __forceinline__ float ex2f(float x) {
    float y; asm("ex2.approx.ftz.f32 %0, %1;" : "=f"(y) : "f"(x)); return y;
}
__device__ __forceinline__ u64 pk2(float lo, float hi) {
    u64 r; asm("mov.b64 %0, {%1, %2};" : "=l"(r) : "f"(lo), "f"(hi)); return r;
}
__device__ __forceinline__ void upk2(u64 v, float& lo, float& hi) {
    asm("mov.b64 {%0, %1}, %2;" : "=f"(lo), "=f"(hi) : "l"(v));
}
__device__ __forceinline__ u64 fma2(u64 a, u64 b, u64 c) {
    u64 d; asm("fma.rn.f32x2 %0, %1, %2, %3;" : "=l"(d) : "l"(a), "l"(b), "l"(c)); return d;
}
__device__ __forceinline__ u64 mul2(u64 a, u64 b) {
    u64 d; asm("mul.rn.f32x2 %0, %1, %2;" : "=l"(d) : "l"(a), "l"(b)); return d;
}
__device__ __forceinline__ u64 add2(u64 a, u64 b) {
    u64 d; asm("add.rn.f32x2 %0, %1, %2;" : "=l"(d) : "l"(a), "l"(b)); return d;
}

// ---------------------------------------------------------------------------
// Fused kernel (R13 structure): per-CTA K/V projection + attention partials.
// K/V key-pair packed: u64 = (val[key 2j], val[key 2j+1]) per dim.
// Build uses ALL 128 threads (1 token each, scalar STS into packed slots).
// QPT=4 for ILP; bounded scores -> no max; scale folded into Wk.
// ---------------------------------------------------------------------------
__global__ void __launch_bounds__(THREADS)
attn_kernel(const float* __restrict__ x,
            const float* __restrict__ theta,
            const float* __restrict__ Wk,
            const float* __restrict__ Wv) {
    __shared__ ulonglong2 Ka[KT/2];      // (d0 pair, d1 pair) per key-pair
    __shared__ ulonglong2 Kb[KT/2];      // (d2 pair, d3 pair)
    __shared__ ulonglong2 Va[KT/2];
    __shared__ ulonglong2 Vb[KT/2];
    __shared__ float wk[DK * EE];
    __shared__ float wv[DK * EE];

    int tid = threadIdx.x;               // 0..127
    int qb  = blockIdx.x;                // 0..3
    int bh  = blockIdx.y;                // 0..15
    int ks  = blockIdx.z;                // 0..15
    int b = bh >> 2, h = bh & 3;

    const float SCL = 0.72134752044448170368f;   // 0.5 * log2(e)
    if (tid < DK * EE) {
        wk[tid] = Wk[h * DK * EE + tid] * SCL;   // fold score scale into K
        wv[tid] = Wv[h * DK * EE + tid];
    }

    // ---- queries: q = cos(x+theta), duplicated-packed (scale is in K) ----
    const float4 thv = *reinterpret_cast<const float4*>(theta + h * DK);
    u64 qd0[QPT], qd1[QPT], qd2[QPT], qd3[QPT];
    int sq0 = qb * QBLK + tid;
    #pragma unroll
    for (int qi = 0; qi < QPT; qi++) {
        int sq = sq0 + qi * THREADS;
        const float4 xq = *reinterpret_cast<const float4*>(
            x + (b * SS + sq) * EE + h * DK);
        float c0 = __cosf(xq.x + thv.x);
        float c1 = __cosf(xq.y + thv.y);
        float c2 = __cosf(xq.z + thv.z);
        float c3 = __cosf(xq.w + thv.w);
        qd0[qi] = pk2(c0, c0); qd1[qi] = pk2(c1, c1);
        qd2[qi] = pk2(c2, c2); qd3[qi] = pk2(c3, c3);
    }
    __syncthreads();

    // ---- K/V tile build: ALL threads, one token each, scalar stores ----
    {
        int tok = tid;                   // KT == THREADS
        const float4* x4 = reinterpret_cast<const float4*>(
            x + ((b * SS + ks * KT) + tok) * EE);
        float xr[EE];
        #pragma unroll
        for (int r = 0; r < 4; r++) {
            float4 q = x4[r];
            xr[4*r+0] = q.x; xr[4*r+1] = q.y; xr[4*r+2] = q.z; xr[4*r+3] = q.w;
        }
        float kk[DK], vv[DK];
        #pragma unroll
        for (int d = 0; d < DK; d++) {
            float a = 0.f, c = 0.f;
            #pragma unroll
            for (int e = 0; e < EE; e++) {
                a = fmaf(xr[e], wk[d * EE + e], a);
                c = fmaf(xr[e], wv[d * EE + e], c);
            }
            kk[d] = a; vv[d] = c;
        }
        // packed slot: pair j = tok>>1, parity = tok&1
        int j = tok >> 1, par = tok & 1;
        float* kaf = reinterpret_cast<float*>(Ka) + j * 4 + par;
        float* kbf = reinterpret_cast<float*>(Kb) + j * 4 + par;
        float* vaf = reinterpret_cast<float*>(Va) + j * 4 + par;
        float* vbf = reinterpret_cast<float*>(Vb) + j * 4 + par;
        kaf[0] = kk[0]; kaf[2] = kk[1];
        kbf[0] = kk[2]; kbf[2] = kk[3];
        vaf[0] = vv[0]; vaf[2] = vv[1];
        vbf[0] = vv[2]; vbf[2] = vv[3];
    }
    __syncthreads();

    u64 A0[QPT], A1[QPT], A2[QPT], A3[QPT], L[QPT];
    #pragma unroll
    for (int qi = 0; qi < QPT; qi++) {
        A0[qi] = 0ULL; A1[qi] = 0ULL; A2[qi] = 0ULL; A3[qi] = 0ULL; L[qi] = 0ULL;
    }

    #pragma unroll 4
    for (int jp = 0; jp < KT/2; jp++) {
        ulonglong2 ka = Ka[jp];              // broadcast LDS.128
        ulonglong2 kb = Kb[jp];
        ulonglong2 va = Va[jp];
        ulonglong2 vb = Vb[jp];
        #pragma unroll
        for (int qi = 0; qi < QPT; qi++) {
            u64 s = mul2(qd0[qi], ka.x);
            s = fma2(qd1[qi], ka.y, s);
            s = fma2(qd2[qi], kb.x, s);
            s = fma2(qd3[qi], kb.y, s);       // (score_even, score_odd)
            float se, so; upk2(s, se, so);
            u64 pp = pk2(ex2f(se), ex2f(so));
            L[qi]  = add2(L[qi], pp);
            A0[qi] = fma2(pp, va.x, A0[qi]);
            A1[qi] = fma2(pp, va.y, A1[qi]);
            A2[qi] = fma2(pp, vb.x, A2[qi]);
            A3[qi] = fma2(pp, vb.y, A3[qi]);
        }
    }

    // coalesced partial stores: [ks][h][b][sq] (lane-consecutive sq)
    int rowbase = ((ks * HH + h) * BB + b) * SS;
    #pragma unroll
    for (int qi = 0; qi < QPT; qi++) {
        int sq = sq0 + qi * THREADS;
        int idx = rowbase + sq;
        float e0, o0, e1, o1, e2, o2, e3, o3, le, lo;
        upk2(A0[qi], e0, o0); upk2(A1[qi], e1, o1);
        upk2(A2[qi], e2, o2); upk2(A3[qi], e3, o3);
        upk2(L[qi], le, lo);
        reinterpret_cast<float4*>(g_parta)[idx] =
            make_float4(e0 + o0, e1 + o1, e2 + o2, e3 + o3);
        g_partl[idx] = le + lo;
    }
}

// ---------------------------------------------------------------------------
// Epilogue (FROZEN, round-13 best): CTA = 16 tokens, 256 threads.
// Thread = (sg = tid>>6, token-head = tid&63); 4 ks-planes per thread,
// 4-lines/LDG; smem combine (stride-5); 64 threads do out = att @ Wc^T.
// ---------------------------------------------------------------------------
#define EPI_TOK 16
#define EPI_THREADS 256
#define SPLANE (BB * SS)     // float4-row stride between h groups

__global__ void __launch_bounds__(EPI_THREADS)
epi_kernel(const float* __restrict__ Wc, float* __restrict__ out) {
    __shared__ float wct[EE * EE];            // wct[e*16+o] = Wc[o*16+e]
    __shared__ float ps[4 * 64 * 5];          // [sg][token-head][5], stride-5
    __shared__ float att[EPI_TOK][EE + 1];

    int tid = threadIdx.x;                    // 0..255
    wct[(tid & 15) * EE + (tid >> 4)] = Wc[tid];

    int sg    = tid >> 6;                     // split-group 0..3 (4 ks each)
    int local = tid & 63;                     // token-head
    int tl = local >> 2;                      // local token 0..15
    int h  = local & 3;
    int tok = blockIdx.x * EPI_TOK + tl;
    int b  = tok >> 11;
    int sq = tok & (SS - 1);

    const float4* pa = reinterpret_cast<const float4*>(g_parta);
    const float*  pl = g_partl;
    int base = (h * BB + b) * SS + sq;        // ks=0 row
    int i0 = base + (sg * 4 + 0) * (HH * SPLANE);
    int i1 = base + (sg * 4 + 1) * (HH * SPLANE);
    int i2 = base + (sg * 4 + 2) * (HH * SPLANE);
    int i3 = base + (sg * 4 + 3) * (HH * SPLANE);

    float4 t0 = pa[i0], t1 = pa[i1], t2 = pa[i2], t3 = pa[i3];
    float  u0 = pl[i0], u1 = pl[i1], u2 = pl[i2], u3 = pl[i3];

    float ax = (t0.x + t1.x) + (t2.x + t3.x);
    float ay = (t0.y + t1.y) + (t2.y + t3.y);
    float az = (t0.z + t1.z) + (t2.z + t3.z);
    float aw = (t0.w + t1.w) + (t2.w + t3.w);
    float l  = (u0 + u1) + (u2 + u3);

    float* row = ps + tid * 5;                // stride 5: conflict-free
    row[0] = ax; row[1] = ay; row[2] = az; row[3] = aw; row[4] = l;
    __syncthreads();

    if (tid < 64) {
        const float* p0 = ps + tid * 5;
        const float* p1 = p0 + 64 * 5;
        const float* p2 = p1 + 64 * 5;
        const float* p3 = p2 + 64 * 5;
        float a0 = (p0[0] + p1[0]) + (p2[0] + p3[0]);
        float a1 = (p0[1] + p1[1]) + (p2[1] + p3[1]);
        float a2 = (p0[2] + p1[2]) + (p2[2] + p3[2]);
        float a3 = (p0[3] + p1[3]) + (p2[3] + p3[3]);
        float ll = (p0[4] + p1[4]) + (p2[4] + p3[4]);
        float inv = 1.0f / ll;
        float* arow = att[tl] + h * DK;
        arow[0] = a0 * inv; arow[1] = a1 * inv;
        arow[2] = a2 * inv; arow[3] = a3 * inv;
    }
    __syncthreads();

    if (tid < 64) {
        const float* ar = att[tl];
        float r[4] = {0.f, 0.f, 0.f, 0.f};
        #pragma unroll
        for (int e = 0; e < EE; e++) {
            float av = ar[e];
            #pragma unroll
            for (int d = 0; d < 4; d++)
                r[d] = fmaf(av, wct[e * EE + h * 4 + d], r[d]);
        }
        reinterpret_cast<float4*>(out + tok * EE)[h] =
            make_float4(r[0], r[1], r[2], r[3]);
    }
}

// ---------------------------------------------------------------------------
extern "C" void kernel_launch(void* const* d_in, const int* in_sizes, int n_in,
                              void* d_out, int out_size) {
    const float* x     = (const float*)d_in[0];
    const float* theta = (const float*)d_in[1];
    const float* Wk    = (const float*)d_in[2];
    const float* Wv    = (const float*)d_in[3];
    const float* Wc    = (const float*)d_in[4];
    float* out = (float*)d_out;

    attn_kernel<<<dim3(SS / QBLK, NBH, KSPLIT), THREADS>>>(x, theta, Wk, Wv);
    epi_kernel<<<(BB * SS) / EPI_TOK, EPI_THREADS>>>(Wc, out);
}